// round 7
// baseline (speedup 1.0000x reference)
#include <cuda_runtime.h>

#define N_FWD  8192
#define T_LEN  4096
#define PAD    2048
#define B_MAX  64
#define FROW   4104           // g_F row stride in float2 (4097 rounded up)
#define FTH    1024
#define ITH    512

// Padded smem indexing: conflict-free radix-8 Stockham writes.
#define PHYS(i) ((i) + ((i) >> 3))
#define FWD_PAD 9216          // PHYS(8191)=9214 -> 9216
#define INV_PAD 4608          // PHYS(4095)=4606 -> 4608

#define LOG_OFF (-9.0109133472792881f)   // -ln(8192): folds 1/n into the log

__device__ float2 g_tw[4096];          // e^{-2 pi i k/8192}, k<4096
__device__ float2 g_tw4k[4096];        // e^{+2 pi i k/4096}, k<4096 (inv twiddles)
__device__ float2 g_F[B_MAX * FROW];   // half spectra F[k], k in [0,4096]

// ---------------------------------------------------------------------------
__global__ void twiddle_init_kernel() {
    int k = blockIdx.x * blockDim.x + threadIdx.x;
    if (k < 4096) {
        float s, c;
        sincospif((float)k * (1.0f / 4096.0f), &s, &c);
        g_tw[k] = make_float2(c, -s);
        float s2, c2;
        sincospif((float)k * (1.0f / 2048.0f), &s2, &c2);
        g_tw4k[k] = make_float2(c2, s2);
    }
}

// ---------------------------------------------------------------------------
// In-register radix-8 butterfly. FWD: e^{-2pi i jr/8}; INV: e^{+...}.
// ---------------------------------------------------------------------------
template<bool FWD>
__device__ __forceinline__ void bfly8(float* xr, float* xi)
{
    const float C = 0.70710678118654752440f;
    float t0r=xr[0]+xr[4], t0i=xi[0]+xi[4];
    float t4r=xr[0]-xr[4], t4i=xi[0]-xi[4];
    float t1r=xr[1]+xr[5], t1i=xi[1]+xi[5];
    float t5r=xr[1]-xr[5], t5i=xi[1]-xi[5];
    float t2r=xr[2]+xr[6], t2i=xi[2]+xi[6];
    float t6r=xr[2]-xr[6], t6i=xi[2]-xi[6];
    float t3r=xr[3]+xr[7], t3i=xi[3]+xi[7];
    float t7r=xr[3]-xr[7], t7i=xi[3]-xi[7];

    float u0r=t0r+t2r, u0i=t0i+t2i;
    float u1r=t0r-t2r, u1i=t0i-t2i;
    float u2r=t1r+t3r, u2i=t1i+t3i;
    float u3r=t1r-t3r, u3i=t1i-t3i;
    xr[0]=u0r+u2r; xi[0]=u0i+u2i;
    xr[4]=u0r-u2r; xi[4]=u0i-u2i;
    if (FWD) { xr[2]=u1r+u3i; xi[2]=u1i-u3r; xr[6]=u1r-u3i; xi[6]=u1i+u3r; }
    else     { xr[2]=u1r-u3i; xi[2]=u1i+u3r; xr[6]=u1r+u3i; xi[6]=u1i-u3r; }

    float a5r,a5i,a6r,a6i,a7r,a7i;
    if (FWD) {
        a5r =  C*(t5r+t5i);  a5i =  C*(t5i-t5r);
        a6r =  t6i;          a6i = -t6r;
        a7r =  C*(t7i-t7r);  a7i = -C*(t7r+t7i);
    } else {
        a5r =  C*(t5r-t5i);  a5i =  C*(t5r+t5i);
        a6r = -t6i;          a6i =  t6r;
        a7r = -C*(t7r+t7i);  a7i =  C*(t7r-t7i);
    }
    float v0r=t4r+a6r, v0i=t4i+a6i;
    float v1r=t4r-a6r, v1i=t4i-a6i;
    float v2r=a5r+a7r, v2i=a5i+a7i;
    float v3r=a5r-a7r, v3i=a5i-a7i;
    xr[1]=v0r+v2r; xi[1]=v0i+v2i;
    xr[5]=v0r-v2r; xi[5]=v0i-v2i;
    if (FWD) { xr[3]=v1r+v3i; xi[3]=v1i-v3r; xr[7]=v1r-v3i; xi[7]=v1i+v3r; }
    else     { xr[3]=v1r-v3i; xi[3]=v1i+v3r; xr[7]=v1r+v3i; xi[7]=v1i-v3r; }
}

// Forward store: twiddle powers via repeated squaring (fwd kernel only).
__device__ __forceinline__ void store8(float* dr, float* di,
                                       const float* xr, const float* xi,
                                       int o, int m, float w1r, float w1i)
{
    float w2r = w1r*w1r - w1i*w1i, w2i = 2.0f*w1r*w1i;
    float w3r = w2r*w1r - w2i*w1i, w3i = w2r*w1i + w2i*w1r;
    float w4r = w2r*w2r - w2i*w2i, w4i = 2.0f*w2r*w2i;
    float w5r = w4r*w1r - w4i*w1i, w5i = w4r*w1i + w4i*w1r;
    float w6r = w3r*w3r - w3i*w3i, w6i = 2.0f*w3r*w3i;
    float w7r = w4r*w3r - w4i*w3i, w7i = w4r*w3i + w4i*w3r;

    int p;
    p = PHYS(o);         dr[p] = xr[0];                     di[p] = xi[0];
    p = PHYS(o + m);     dr[p] = xr[1]*w1r - xi[1]*w1i;     di[p] = xr[1]*w1i + xi[1]*w1r;
    p = PHYS(o + 2*m);   dr[p] = xr[2]*w2r - xi[2]*w2i;     di[p] = xr[2]*w2i + xi[2]*w2r;
    p = PHYS(o + 3*m);   dr[p] = xr[3]*w3r - xi[3]*w3i;     di[p] = xr[3]*w3i + xi[3]*w3r;
    p = PHYS(o + 4*m);   dr[p] = xr[4]*w4r - xi[4]*w4i;     di[p] = xr[4]*w4i + xi[4]*w4r;
    p = PHYS(o + 5*m);   dr[p] = xr[5]*w5r - xi[5]*w5i;     di[p] = xr[5]*w5i + xi[5]*w5r;
    p = PHYS(o + 6*m);   dr[p] = xr[6]*w6r - xi[6]*w6i;     di[p] = xr[6]*w6i + xi[6]*w6r;
    p = PHYS(o + 7*m);   dr[p] = xr[7]*w7r - xi[7]*w7i;     di[p] = xr[7]*w7i + xi[7]*w7r;
}

// Inverse store: twiddle powers W^r = TW[jm*r] from the per-CTA smem table.
// Additive pointer stepping keeps index math on the alu pipe.
__device__ __forceinline__ void store8_tbl(float* dr, float* di,
                                           const float* xr, const float* xi,
                                           int o, int m, int jm,
                                           const float2* __restrict__ TW)
{
    int p = PHYS(o);
    dr[p] = xr[0]; di[p] = xi[0];
    const float2* wp = TW + jm;
    #pragma unroll
    for (int r = 1; r < 8; ++r) {
        float2 W = *wp;
        wp += jm;
        int pp = PHYS(o + r * m);
        dr[pp] = xr[r] * W.x - xi[r] * W.y;
        di[pp] = xr[r] * W.y + xi[r] * W.x;
    }
}

// ===========================================================================
// Forward 8192-pt FFT (radix-8 x4 + radix-2), one CTA per batch row.
// ===========================================================================
__device__ __forceinline__ void fwd_stage(const float* sr, const float* si,
                                          float* dr, float* di, int m, int tid)
{
    float xr[8], xi[8];
    #pragma unroll
    for (int q = 0; q < 8; ++q) {
        int p = PHYS(tid + q * 1024);
        xr[q] = sr[p]; xi[q] = si[p];
    }
    bfly8<true>(xr, xi);
    int k = tid & (m - 1), jm = tid - k;
    float2 t = g_tw[jm];
    store8(dr, di, xr, xi, 8 * jm + k, m, t.x, t.y);
}

extern __shared__ float sm_[];

__global__ void __launch_bounds__(FTH, 1)
fwd_fft_kernel(const float* __restrict__ in)
{
    float* Ar = sm_;
    float* Ai = sm_ + FWD_PAD;
    float* Br = sm_ + 2 * FWD_PAD;
    float* Bi = sm_ + 3 * FWD_PAD;

    const int b = blockIdx.x, tid = threadIdx.x;
    const float* x = in + b * T_LEN;

    {
        float xr[8], xi[8];
        #pragma unroll
        for (int q = 0; q < 8; ++q) {
            int i = tid + q * 1024;
            int src;
            if (i < PAD)              src = PAD - 1 - i;
            else if (i < PAD + T_LEN) src = i - PAD;
            else                      src = (2 * T_LEN + PAD - 1) - i;
            xr[q] = x[src]; xi[q] = 0.0f;
        }
        bfly8<true>(xr, xi);
        float2 t = g_tw[tid];
        store8(Ar, Ai, xr, xi, 8 * tid, 1, t.x, t.y);
    }
    __syncthreads();
    fwd_stage(Ar, Ai, Br, Bi,   8, tid); __syncthreads();
    fwd_stage(Br, Bi, Ar, Ai,  64, tid); __syncthreads();
    fwd_stage(Ar, Ai, Br, Bi, 512, tid); __syncthreads();

    float2* Fo = g_F + b * FROW;
    #pragma unroll
    for (int q = 0; q < 4; ++q) {
        int k = tid + q * 1024;
        float ur = Br[PHYS(k)],        ui = Bi[PHYS(k)];
        float vr = Br[PHYS(k + 4096)], vi = Bi[PHYS(k + 4096)];
        Fo[k] = make_float2(ur + vr, ui + vi);
        if (k == 0) Fo[4096] = make_float2(ur - vr, ui - vi);
    }
}

// ===========================================================================
// CWT inverse kernel: one CTA per (b,s). Two sequential 4096-pt inverse
// radix-8 Stockham FFTs (even / odd output samples of the 8192-pt IFFT of
// the half-spectrum G = F*wft; 1/n folded into the log). Twiddle powers come
// from a per-CTA smem table (kills the 24-FMA power chains). Pass-0 log
// values held in registers; pass-1 emits coalesced float2 stores.
// ===========================================================================
__device__ __forceinline__ void inv_stage(const float* sr, const float* si,
                                          float* dr, float* di, int m, int tid,
                                          const float2* __restrict__ TW)
{
    float xr[8], xi[8];
    #pragma unroll
    for (int q = 0; q < 8; ++q) {
        int p = PHYS(tid + q * 512);
        xr[q] = sr[p]; xi[q] = si[p];
    }
    bfly8<false>(xr, xi);
    int k = tid & (m - 1), jm = tid - k;
    store8_tbl(dr, di, xr, xi, 8 * jm + k, m, jm, TW);
}

__global__ void __launch_bounds__(ITH, 2)
cwt_kernel(const float* __restrict__ wft, float* __restrict__ out, int S)
{
    float*  Ar = sm_;
    float*  Ai = sm_ + INV_PAD;
    float*  Br = sm_ + 2 * INV_PAD;
    float*  Bi = sm_ + 3 * INV_PAD;
    float2* TW = (float2*)(sm_ + 4 * INV_PAD);   // 4096 float2 = 32 KB

    const int tid = threadIdx.x;
    const int s = blockIdx.x % S, b = blockIdx.x / S;
    const float2* __restrict__ F = g_F + b * FROW;
    const float*  __restrict__ w = wft + (size_t)s * N_FWD;

    // per-CTA twiddle table (amortized over both passes)
    #pragma unroll
    for (int q = 0; q < 8; ++q)
        TW[tid + q * ITH] = g_tw4k[tid + q * ITH];

    float2 fn = F[4096];
    float  gn = w[4096];
    float  nyr = fn.x * gn, nyi = fn.y * gn;

    float ev[4];     // pass-0 log values (same thread & columns in pass 1)

    __syncthreads();

    #pragma unroll
    for (int pass = 0; pass < 2; ++pass) {
        float xr[8], xi[8];

        // stage m=1 fused with global load + spectrum multiply (+odd rotation)
        #pragma unroll
        for (int q = 0; q < 8; ++q) {
            int k = tid + q * 512;
            float2 f = F[k];
            float  g = w[k];
            float vr = f.x * g, vi = f.y * g;
            if (pass) {                        // * e^{+2 pi i k/8192} = conj(g_tw[k])
                float2 c = g_tw[k];
                float r2 = vr * c.x + vi * c.y;
                float i2 = vi * c.x - vr * c.y;
                vr = r2; vi = i2;
            }
            xr[q] = vr; xi[q] = vi;
        }
        bfly8<false>(xr, xi);
        store8_tbl(Ar, Ai, xr, xi, 8 * tid, 1, tid, TW);
        __syncthreads();
        inv_stage(Ar, Ai, Br, Bi,  8, tid, TW); __syncthreads();
        inv_stage(Br, Bi, Ar, Ai, 64, tid, TW); __syncthreads();

        // final stage m=512 (jm=0, W=1) fused with Nyquist + log|.| + store.
        // Thread tid produces u = tid + 512 r; needed u in [1024,3072) -> r=2..5.
        #pragma unroll
        for (int q = 0; q < 8; ++q) {
            int p = PHYS(tid + q * 512);
            xr[q] = Ar[p]; xi[q] = Ai[p];
        }
        bfly8<false>(xr, xi);

        float nr = pass ? -nyr : nyr;
        float ni = pass ? -nyi : nyi;
        if (pass == 0) {
            #pragma unroll
            for (int r = 2; r <= 5; ++r) {
                float a = xr[r] + nr, bb = xi[r] + ni;
                ev[r - 2] = fmaf(0.5f, __logf(a * a + bb * bb), LOG_OFF);
            }
        } else {
            float2* o2 = (float2*)(out + (size_t)blockIdx.x * T_LEN);
            #pragma unroll
            for (int r = 2; r <= 5; ++r) {
                float a = xr[r] + nr, bb = xi[r] + ni;
                float lg = fmaf(0.5f, __logf(a * a + bb * bb), LOG_OFF);
                o2[tid + 512 * (r - 2)] = make_float2(ev[r - 2], lg);
            }
        }
        __syncthreads();
    }
}

// ---------------------------------------------------------------------------
extern "C" void kernel_launch(void* const* d_in, const int* in_sizes, int n_in,
                              void* d_out, int out_size)
{
    const float* in  = (const float*)d_in[0];
    const float* wft = (const float*)d_in[1];
    float* out = (float*)d_out;

    const int B = in_sizes[0] / T_LEN;     // 64
    const int S = in_sizes[1] / N_FWD;     // 75

    const int fwd_smem = 4 * FWD_PAD * sizeof(float);                    // 147456 B
    const int cwt_smem = 4 * INV_PAD * sizeof(float) + 4096 * 8;         // 106496 B
    cudaFuncSetAttribute(fwd_fft_kernel,
                         cudaFuncAttributeMaxDynamicSharedMemorySize, fwd_smem);
    cudaFuncSetAttribute(cwt_kernel,
                         cudaFuncAttributeMaxDynamicSharedMemorySize, cwt_smem);

    twiddle_init_kernel<<<16, 256>>>();
    fwd_fft_kernel<<<B, FTH, fwd_smem>>>(in);
    cwt_kernel<<<B * S, ITH, cwt_smem>>>(wft, out, S);
}

// round 8
// speedup vs baseline: 1.0910x; 1.0910x over previous
#include <cuda_runtime.h>

#define N_FWD  8192
#define T_LEN  4096
#define PAD    2048
#define B_MAX  64
#define FROW   4104           // g_F row stride in float2 (4097 rounded up)
#define FTH    1024
#define ITH    512

// Padded smem indexing: conflict-free radix-8 Stockham writes.
#define PHYS(i) ((i) + ((i) >> 3))
#define FWD_PAD 9216          // PHYS(8191)=9214 -> 9216
#define INV_PAD 4608          // PHYS(4095)=4606 -> 4608

#define LOG_OFF (-9.0109133472792881f)   // -ln(8192): folds 1/n into the log

__device__ float2 g_tw[4096];          // e^{-2 pi i k/8192}, k<4096
__device__ float2 g_F[B_MAX * FROW];   // half spectra F[k], k in [0,4096]

// ---------------------------------------------------------------------------
__global__ void twiddle_init_kernel() {
    int k = blockIdx.x * blockDim.x + threadIdx.x;
    if (k < 4096) {
        float s, c;
        sincospif((float)k * (1.0f / 4096.0f), &s, &c);
        g_tw[k] = make_float2(c, -s);
    }
}

// ---------------------------------------------------------------------------
// In-register radix-8 butterfly. FWD: e^{-2pi i jr/8}; INV: e^{+...}.
// ---------------------------------------------------------------------------
template<bool FWD>
__device__ __forceinline__ void bfly8(float* xr, float* xi)
{
    const float C = 0.70710678118654752440f;
    float t0r=xr[0]+xr[4], t0i=xi[0]+xi[4];
    float t4r=xr[0]-xr[4], t4i=xi[0]-xi[4];
    float t1r=xr[1]+xr[5], t1i=xi[1]+xi[5];
    float t5r=xr[1]-xr[5], t5i=xi[1]-xi[5];
    float t2r=xr[2]+xr[6], t2i=xi[2]+xi[6];
    float t6r=xr[2]-xr[6], t6i=xi[2]-xi[6];
    float t3r=xr[3]+xr[7], t3i=xi[3]+xi[7];
    float t7r=xr[3]-xr[7], t7i=xi[3]-xi[7];

    float u0r=t0r+t2r, u0i=t0i+t2i;
    float u1r=t0r-t2r, u1i=t0i-t2i;
    float u2r=t1r+t3r, u2i=t1i+t3i;
    float u3r=t1r-t3r, u3i=t1i-t3i;
    xr[0]=u0r+u2r; xi[0]=u0i+u2i;
    xr[4]=u0r-u2r; xi[4]=u0i-u2i;
    if (FWD) { xr[2]=u1r+u3i; xi[2]=u1i-u3r; xr[6]=u1r-u3i; xi[6]=u1i+u3r; }
    else     { xr[2]=u1r-u3i; xi[2]=u1i+u3r; xr[6]=u1r+u3i; xi[6]=u1i-u3r; }

    float a5r,a5i,a6r,a6i,a7r,a7i;
    if (FWD) {
        a5r =  C*(t5r+t5i);  a5i =  C*(t5i-t5r);
        a6r =  t6i;          a6i = -t6r;
        a7r =  C*(t7i-t7r);  a7i = -C*(t7r+t7i);
    } else {
        a5r =  C*(t5r-t5i);  a5i =  C*(t5r+t5i);
        a6r = -t6i;          a6i =  t6r;
        a7r = -C*(t7r+t7i);  a7i =  C*(t7r-t7i);
    }
    float v0r=t4r+a6r, v0i=t4i+a6i;
    float v1r=t4r-a6r, v1i=t4i-a6i;
    float v2r=a5r+a7r, v2i=a5i+a7i;
    float v3r=a5r-a7r, v3i=a5i-a7i;
    xr[1]=v0r+v2r; xi[1]=v0i+v2i;
    xr[5]=v0r-v2r; xi[5]=v0i-v2i;
    if (FWD) { xr[3]=v1r+v3i; xi[3]=v1i-v3r; xr[7]=v1r-v3i; xi[7]=v1i+v3r; }
    else     { xr[3]=v1r-v3i; xi[3]=v1i+v3r; xr[7]=v1r+v3i; xi[7]=v1i-v3r; }
}

// Store 8 outputs with twiddles w1^r. Powers via repeated squaring
// (dependency depth 3; register-only — no memory-sourced twiddles).
__device__ __forceinline__ void store8(float* dr, float* di,
                                       const float* xr, const float* xi,
                                       int o, int m, float w1r, float w1i)
{
    float w2r = w1r*w1r - w1i*w1i, w2i = 2.0f*w1r*w1i;
    float w3r = w2r*w1r - w2i*w1i, w3i = w2r*w1i + w2i*w1r;
    float w4r = w2r*w2r - w2i*w2i, w4i = 2.0f*w2r*w2i;
    float w5r = w4r*w1r - w4i*w1i, w5i = w4r*w1i + w4i*w1r;
    float w6r = w3r*w3r - w3i*w3i, w6i = 2.0f*w3r*w3i;
    float w7r = w4r*w3r - w4i*w3i, w7i = w4r*w3i + w4i*w3r;

    int p;
    p = PHYS(o);         dr[p] = xr[0];                     di[p] = xi[0];
    p = PHYS(o + m);     dr[p] = xr[1]*w1r - xi[1]*w1i;     di[p] = xr[1]*w1i + xi[1]*w1r;
    p = PHYS(o + 2*m);   dr[p] = xr[2]*w2r - xi[2]*w2i;     di[p] = xr[2]*w2i + xi[2]*w2r;
    p = PHYS(o + 3*m);   dr[p] = xr[3]*w3r - xi[3]*w3i;     di[p] = xr[3]*w3i + xi[3]*w3r;
    p = PHYS(o + 4*m);   dr[p] = xr[4]*w4r - xi[4]*w4i;     di[p] = xr[4]*w4i + xi[4]*w4r;
    p = PHYS(o + 5*m);   dr[p] = xr[5]*w5r - xi[5]*w5i;     di[p] = xr[5]*w5i + xi[5]*w5r;
    p = PHYS(o + 6*m);   dr[p] = xr[6]*w6r - xi[6]*w6i;     di[p] = xr[6]*w6i + xi[6]*w6r;
    p = PHYS(o + 7*m);   dr[p] = xr[7]*w7r - xi[7]*w7i;     di[p] = xr[7]*w7i + xi[7]*w7r;
}

// ===========================================================================
// Forward 8192-pt FFT (radix-8 x4 + radix-2), one CTA per batch row.
// ===========================================================================
__device__ __forceinline__ void fwd_stage(const float* sr, const float* si,
                                          float* dr, float* di, int m, int tid)
{
    float xr[8], xi[8];
    #pragma unroll
    for (int q = 0; q < 8; ++q) {
        int p = PHYS(tid + q * 1024);
        xr[q] = sr[p]; xi[q] = si[p];
    }
    bfly8<true>(xr, xi);
    int k = tid & (m - 1), jm = tid - k;
    float2 t = g_tw[jm];
    store8(dr, di, xr, xi, 8 * jm + k, m, t.x, t.y);
}

extern __shared__ float sm_[];

__global__ void __launch_bounds__(FTH, 1)
fwd_fft_kernel(const float* __restrict__ in)
{
    float* Ar = sm_;
    float* Ai = sm_ + FWD_PAD;
    float* Br = sm_ + 2 * FWD_PAD;
    float* Bi = sm_ + 3 * FWD_PAD;

    const int b = blockIdx.x, tid = threadIdx.x;
    const float* x = in + b * T_LEN;

    {
        float xr[8], xi[8];
        #pragma unroll
        for (int q = 0; q < 8; ++q) {
            int i = tid + q * 1024;
            int src;
            if (i < PAD)              src = PAD - 1 - i;
            else if (i < PAD + T_LEN) src = i - PAD;
            else                      src = (2 * T_LEN + PAD - 1) - i;
            xr[q] = x[src]; xi[q] = 0.0f;
        }
        bfly8<true>(xr, xi);
        float2 t = g_tw[tid];
        store8(Ar, Ai, xr, xi, 8 * tid, 1, t.x, t.y);
    }
    __syncthreads();
    fwd_stage(Ar, Ai, Br, Bi,   8, tid); __syncthreads();
    fwd_stage(Br, Bi, Ar, Ai,  64, tid); __syncthreads();
    fwd_stage(Ar, Ai, Br, Bi, 512, tid); __syncthreads();

    float2* Fo = g_F + b * FROW;
    #pragma unroll
    for (int q = 0; q < 4; ++q) {
        int k = tid + q * 1024;
        float ur = Br[PHYS(k)],        ui = Bi[PHYS(k)];
        float vr = Br[PHYS(k + 4096)], vi = Bi[PHYS(k + 4096)];
        Fo[k] = make_float2(ur + vr, ui + vi);
        if (k == 0) Fo[4096] = make_float2(ur - vr, ui - vi);
    }
}

// ===========================================================================
// CWT inverse kernel: one CTA per (b,s). Two sequential 4096-pt inverse
// radix-8 Stockham FFTs (even / odd output samples of the 8192-pt IFFT of
// the half-spectrum G = F*wft; 1/n folded into the log constant).
// Pass 0 caches G in smem; pass 1 reads it back via coalesced LDS instead
// of re-loading F and wft from L2. Pass-0 log values held in registers;
// pass-1 emits coalesced float2 stores.
// ===========================================================================
__device__ __forceinline__ void inv_stage(const float* sr, const float* si,
                                          float* dr, float* di, int m, int tid)
{
    float xr[8], xi[8];
    #pragma unroll
    for (int q = 0; q < 8; ++q) {
        int p = PHYS(tid + q * 512);
        xr[q] = sr[p]; xi[q] = si[p];
    }
    bfly8<false>(xr, xi);
    int k = tid & (m - 1), jm = tid - k;
    float2 t = g_tw[jm << 1];             // e^{-2pi i jm/4096}; conj below
    store8(dr, di, xr, xi, 8 * jm + k, m, t.x, -t.y);
}

__global__ void __launch_bounds__(ITH, 2)
cwt_kernel(const float* __restrict__ wft, float* __restrict__ out, int S)
{
    float*  Ar = sm_;
    float*  Ai = sm_ + INV_PAD;
    float*  Br = sm_ + 2 * INV_PAD;
    float*  Bi = sm_ + 3 * INV_PAD;
    float2* Gs = (float2*)(sm_ + 4 * INV_PAD);   // 4096 float2 = 32 KB

    const int tid = threadIdx.x;
    const int s = blockIdx.x % S, b = blockIdx.x / S;
    const float2* __restrict__ F = g_F + b * FROW;
    const float*  __restrict__ w = wft + (size_t)s * N_FWD;

    float2 fn = F[4096];
    float  gn = w[4096];
    float  nyr = fn.x * gn, nyi = fn.y * gn;

    float ev[4];     // pass-0 log values (same thread & columns in pass 1)

    #pragma unroll
    for (int pass = 0; pass < 2; ++pass) {
        float xr[8], xi[8];

        // stage m=1 fused with spectrum load/multiply (+odd rotation).
        // Pass 0: G = F*w from global, cached into Gs.
        // Pass 1: G from smem, rotated by conj(g_tw[k]).
        #pragma unroll
        for (int q = 0; q < 8; ++q) {
            int k = tid + q * 512;
            float vr, vi;
            if (pass == 0) {
                float2 f = F[k];
                float  g = w[k];
                vr = f.x * g; vi = f.y * g;
                Gs[k] = make_float2(vr, vi);
            } else {
                float2 gv = Gs[k];
                float2 c  = g_tw[k];       // * e^{+2 pi i k/8192} = conj(g_tw[k])
                vr = gv.x * c.x + gv.y * c.y;
                vi = gv.y * c.x - gv.x * c.y;
            }
            xr[q] = vr; xi[q] = vi;
        }
        bfly8<false>(xr, xi);
        {
            float2 t = g_tw[tid << 1];
            store8(Ar, Ai, xr, xi, 8 * tid, 1, t.x, -t.y);
        }
        __syncthreads();
        inv_stage(Ar, Ai, Br, Bi,  8, tid); __syncthreads();
        inv_stage(Br, Bi, Ar, Ai, 64, tid); __syncthreads();

        // final stage m=512 (jm=0, W=1) fused with Nyquist + log|.| + store.
        // Thread tid produces u = tid + 512 r; needed u in [1024,3072) -> r=2..5.
        #pragma unroll
        for (int q = 0; q < 8; ++q) {
            int p = PHYS(tid + q * 512);
            xr[q] = Ar[p]; xi[q] = Ai[p];
        }
        bfly8<false>(xr, xi);

        float nr = pass ? -nyr : nyr;
        float ni = pass ? -nyi : nyi;
        if (pass == 0) {
            #pragma unroll
            for (int r = 2; r <= 5; ++r) {
                float a = xr[r] + nr, bb = xi[r] + ni;
                ev[r - 2] = fmaf(0.5f, __logf(a * a + bb * bb), LOG_OFF);
            }
        } else {
            float2* o2 = (float2*)(out + (size_t)blockIdx.x * T_LEN);
            #pragma unroll
            for (int r = 2; r <= 5; ++r) {
                float a = xr[r] + nr, bb = xi[r] + ni;
                float lg = fmaf(0.5f, __logf(a * a + bb * bb), LOG_OFF);
                o2[tid + 512 * (r - 2)] = make_float2(ev[r - 2], lg);
            }
        }
        __syncthreads();
    }
}

// ---------------------------------------------------------------------------
extern "C" void kernel_launch(void* const* d_in, const int* in_sizes, int n_in,
                              void* d_out, int out_size)
{
    const float* in  = (const float*)d_in[0];
    const float* wft = (const float*)d_in[1];
    float* out = (float*)d_out;

    const int B = in_sizes[0] / T_LEN;     // 64
    const int S = in_sizes[1] / N_FWD;     // 75

    const int fwd_smem = 4 * FWD_PAD * sizeof(float);              // 147456 B
    const int cwt_smem = 4 * INV_PAD * sizeof(float) + 4096 * 8;   // 106496 B
    cudaFuncSetAttribute(fwd_fft_kernel,
                         cudaFuncAttributeMaxDynamicSharedMemorySize, fwd_smem);
    cudaFuncSetAttribute(cwt_kernel,
                         cudaFuncAttributeMaxDynamicSharedMemorySize, cwt_smem);

    twiddle_init_kernel<<<16, 256>>>();
    fwd_fft_kernel<<<B, FTH, fwd_smem>>>(in);
    cwt_kernel<<<B * S, ITH, cwt_smem>>>(wft, out, S);
}

// round 9
// speedup vs baseline: 1.1544x; 1.0581x over previous
#include <cuda_runtime.h>

#define N_FWD  8192
#define T_LEN  4096
#define PAD    2048
#define B_MAX  64
#define FROW   4104           // g_F row stride in float2 (4097 rounded up)
#define FTH    1024
#define ITH    512

// Scalar padding (fwd kernel, two scalar arrays)
#define PHYS(i) ((i) + ((i) >> 3))
#define FWD_PAD 9216          // PHYS(8191)=9214 -> 9216
// Complex padding (cwt kernel, interleaved float2 array)
#define CPAD(i) ((i) + ((i) >> 3))
#define INV_CPAD 4608         // CPAD(4095)=4606 -> 4608 float2

#define LOG_OFF (-9.0109133472792881f)   // -ln(8192): folds 1/n into the log

__device__ float2 g_tw[4096];          // e^{-2 pi i k/8192}, k<4096
__device__ float2 g_F[B_MAX * FROW];   // half spectra F[k], k in [0,4096]

// ---------------------------------------------------------------------------
__global__ void twiddle_init_kernel() {
    int k = blockIdx.x * blockDim.x + threadIdx.x;
    if (k < 4096) {
        float s, c;
        sincospif((float)k * (1.0f / 4096.0f), &s, &c);
        g_tw[k] = make_float2(c, -s);
    }
}

// ---------------------------------------------------------------------------
// In-register radix-8 butterfly. FWD: e^{-2pi i jr/8}; INV: e^{+...}.
// ---------------------------------------------------------------------------
template<bool FWD>
__device__ __forceinline__ void bfly8(float* xr, float* xi)
{
    const float C = 0.70710678118654752440f;
    float t0r=xr[0]+xr[4], t0i=xi[0]+xi[4];
    float t4r=xr[0]-xr[4], t4i=xi[0]-xi[4];
    float t1r=xr[1]+xr[5], t1i=xi[1]+xi[5];
    float t5r=xr[1]-xr[5], t5i=xi[1]-xi[5];
    float t2r=xr[2]+xr[6], t2i=xi[2]+xi[6];
    float t6r=xr[2]-xr[6], t6i=xi[2]-xi[6];
    float t3r=xr[3]+xr[7], t3i=xi[3]+xi[7];
    float t7r=xr[3]-xr[7], t7i=xi[3]-xi[7];

    float u0r=t0r+t2r, u0i=t0i+t2i;
    float u1r=t0r-t2r, u1i=t0i-t2i;
    float u2r=t1r+t3r, u2i=t1i+t3i;
    float u3r=t1r-t3r, u3i=t1i-t3i;
    xr[0]=u0r+u2r; xi[0]=u0i+u2i;
    xr[4]=u0r-u2r; xi[4]=u0i-u2i;
    if (FWD) { xr[2]=u1r+u3i; xi[2]=u1i-u3r; xr[6]=u1r-u3i; xi[6]=u1i+u3r; }
    else     { xr[2]=u1r-u3i; xi[2]=u1i+u3r; xr[6]=u1r+u3i; xi[6]=u1i-u3r; }

    float a5r,a5i,a6r,a6i,a7r,a7i;
    if (FWD) {
        a5r =  C*(t5r+t5i);  a5i =  C*(t5i-t5r);
        a6r =  t6i;          a6i = -t6r;
        a7r =  C*(t7i-t7r);  a7i = -C*(t7r+t7i);
    } else {
        a5r =  C*(t5r-t5i);  a5i =  C*(t5r+t5i);
        a6r = -t6i;          a6i =  t6r;
        a7r = -C*(t7r+t7i);  a7i =  C*(t7r-t7i);
    }
    float v0r=t4r+a6r, v0i=t4i+a6i;
    float v1r=t4r-a6r, v1i=t4i-a6i;
    float v2r=a5r+a7r, v2i=a5i+a7i;
    float v3r=a5r-a7r, v3i=a5i-a7i;
    xr[1]=v0r+v2r; xi[1]=v0i+v2i;
    xr[5]=v0r-v2r; xi[5]=v0i-v2i;
    if (FWD) { xr[3]=v1r+v3i; xi[3]=v1i-v3r; xr[7]=v1r-v3i; xi[7]=v1i+v3r; }
    else     { xr[3]=v1r-v3i; xi[3]=v1i+v3r; xr[7]=v1r+v3i; xi[7]=v1i-v3r; }
}

// ---------------------------------------------------------------------------
// Twiddle powers by repeated squaring (register-only, depth 3).
// ---------------------------------------------------------------------------

// Forward store (scalar arrays, fwd kernel only).
__device__ __forceinline__ void store8(float* dr, float* di,
                                       const float* xr, const float* xi,
                                       int o, int m, float w1r, float w1i)
{
    float w2r = w1r*w1r - w1i*w1i, w2i = 2.0f*w1r*w1i;
    float w3r = w2r*w1r - w2i*w1i, w3i = w2r*w1i + w2i*w1r;
    float w4r = w2r*w2r - w2i*w2i, w4i = 2.0f*w2r*w2i;
    float w5r = w4r*w1r - w4i*w1i, w5i = w4r*w1i + w4i*w1r;
    float w6r = w3r*w3r - w3i*w3i, w6i = 2.0f*w3r*w3i;
    float w7r = w4r*w3r - w4i*w3i, w7i = w4r*w3i + w4i*w3r;

    int p;
    p = PHYS(o);         dr[p] = xr[0];                     di[p] = xi[0];
    p = PHYS(o + m);     dr[p] = xr[1]*w1r - xi[1]*w1i;     di[p] = xr[1]*w1i + xi[1]*w1r;
    p = PHYS(o + 2*m);   dr[p] = xr[2]*w2r - xi[2]*w2i;     di[p] = xr[2]*w2i + xi[2]*w2r;
    p = PHYS(o + 3*m);   dr[p] = xr[3]*w3r - xi[3]*w3i;     di[p] = xr[3]*w3i + xi[3]*w3r;
    p = PHYS(o + 4*m);   dr[p] = xr[4]*w4r - xi[4]*w4i;     di[p] = xr[4]*w4i + xi[4]*w4r;
    p = PHYS(o + 5*m);   dr[p] = xr[5]*w5r - xi[5]*w5i;     di[p] = xr[5]*w5i + xi[5]*w5r;
    p = PHYS(o + 6*m);   dr[p] = xr[6]*w6r - xi[6]*w6i;     di[p] = xr[6]*w6i + xi[6]*w6r;
    p = PHYS(o + 7*m);   dr[p] = xr[7]*w7r - xi[7]*w7i;     di[p] = xr[7]*w7i + xi[7]*w7r;
}

// Inverse store: interleaved complex float2 array (STS.64, conflict-free
// by the CPAD bank permutation; halves smem instruction count).
__device__ __forceinline__ void store8c(float2* d,
                                        const float* xr, const float* xi,
                                        int o, int m, float w1r, float w1i)
{
    float w2r = w1r*w1r - w1i*w1i, w2i = 2.0f*w1r*w1i;
    float w3r = w2r*w1r - w2i*w1i, w3i = w2r*w1i + w2i*w1r;
    float w4r = w2r*w2r - w2i*w2i, w4i = 2.0f*w2r*w2i;
    float w5r = w4r*w1r - w4i*w1i, w5i = w4r*w1i + w4i*w1r;
    float w6r = w3r*w3r - w3i*w3i, w6i = 2.0f*w3r*w3i;
    float w7r = w4r*w3r - w4i*w3i, w7i = w4r*w3i + w4i*w3r;

    d[CPAD(o)]       = make_float2(xr[0],                  xi[0]);
    d[CPAD(o + m)]   = make_float2(xr[1]*w1r - xi[1]*w1i,  xr[1]*w1i + xi[1]*w1r);
    d[CPAD(o + 2*m)] = make_float2(xr[2]*w2r - xi[2]*w2i,  xr[2]*w2i + xi[2]*w2r);
    d[CPAD(o + 3*m)] = make_float2(xr[3]*w3r - xi[3]*w3i,  xr[3]*w3i + xi[3]*w3r);
    d[CPAD(o + 4*m)] = make_float2(xr[4]*w4r - xi[4]*w4i,  xr[4]*w4i + xi[4]*w4r);
    d[CPAD(o + 5*m)] = make_float2(xr[5]*w5r - xi[5]*w5i,  xr[5]*w5i + xi[5]*w5r);
    d[CPAD(o + 6*m)] = make_float2(xr[6]*w6r - xi[6]*w6i,  xr[6]*w6i + xi[6]*w6r);
    d[CPAD(o + 7*m)] = make_float2(xr[7]*w7r - xi[7]*w7i,  xr[7]*w7i + xi[7]*w7r);
}

// ===========================================================================
// Forward 8192-pt FFT (radix-8 x4 + radix-2), one CTA per batch row.
// ===========================================================================
__device__ __forceinline__ void fwd_stage(const float* sr, const float* si,
                                          float* dr, float* di, int m, int tid)
{
    float xr[8], xi[8];
    #pragma unroll
    for (int q = 0; q < 8; ++q) {
        int p = PHYS(tid + q * 1024);
        xr[q] = sr[p]; xi[q] = si[p];
    }
    bfly8<true>(xr, xi);
    int k = tid & (m - 1), jm = tid - k;
    float2 t = g_tw[jm];
    store8(dr, di, xr, xi, 8 * jm + k, m, t.x, t.y);
}

extern __shared__ float sm_[];

__global__ void __launch_bounds__(FTH, 1)
fwd_fft_kernel(const float* __restrict__ in)
{
    float* Ar = sm_;
    float* Ai = sm_ + FWD_PAD;
    float* Br = sm_ + 2 * FWD_PAD;
    float* Bi = sm_ + 3 * FWD_PAD;

    const int b = blockIdx.x, tid = threadIdx.x;
    const float* x = in + b * T_LEN;

    {
        float xr[8], xi[8];
        #pragma unroll
        for (int q = 0; q < 8; ++q) {
            int i = tid + q * 1024;
            int src;
            if (i < PAD)              src = PAD - 1 - i;
            else if (i < PAD + T_LEN) src = i - PAD;
            else                      src = (2 * T_LEN + PAD - 1) - i;
            xr[q] = x[src]; xi[q] = 0.0f;
        }
        bfly8<true>(xr, xi);
        float2 t = g_tw[tid];
        store8(Ar, Ai, xr, xi, 8 * tid, 1, t.x, t.y);
    }
    __syncthreads();
    fwd_stage(Ar, Ai, Br, Bi,   8, tid); __syncthreads();
    fwd_stage(Br, Bi, Ar, Ai,  64, tid); __syncthreads();
    fwd_stage(Ar, Ai, Br, Bi, 512, tid); __syncthreads();

    float2* Fo = g_F + b * FROW;
    #pragma unroll
    for (int q = 0; q < 4; ++q) {
        int k = tid + q * 1024;
        float ur = Br[PHYS(k)],        ui = Bi[PHYS(k)];
        float vr = Br[PHYS(k + 4096)], vi = Bi[PHYS(k + 4096)];
        Fo[k] = make_float2(ur + vr, ui + vi);
        if (k == 0) Fo[4096] = make_float2(ur - vr, ui - vi);
    }
}

// ===========================================================================
// CWT inverse kernel: one CTA per (b,s). Two sequential 4096-pt inverse
// radix-8 Stockham FFTs (even / odd output samples of the 8192-pt IFFT of
// the half-spectrum G = F*wft; 1/n folded into the log constant).
// Interleaved-complex float2 smem halves LDS/STS instruction count.
// Pass-0 log values held in registers; pass-1 emits coalesced float2 stores.
// ===========================================================================
__device__ __forceinline__ void inv_stage(const float2* s, float2* d,
                                          int m, int tid)
{
    float xr[8], xi[8];
    #pragma unroll
    for (int q = 0; q < 8; ++q) {
        float2 v = s[CPAD(tid + q * 512)];
        xr[q] = v.x; xi[q] = v.y;
    }
    bfly8<false>(xr, xi);
    int k = tid & (m - 1), jm = tid - k;
    float2 t = g_tw[jm << 1];             // e^{-2pi i jm/4096}; conj below
    store8c(d, xr, xi, 8 * jm + k, m, t.x, -t.y);
}

__global__ void __launch_bounds__(ITH, 2)
cwt_kernel(const float* __restrict__ wft, float* __restrict__ out, int S)
{
    float2* A  = (float2*)sm_;
    float2* Bb = A + INV_CPAD;

    const int tid = threadIdx.x;
    const int s = blockIdx.x % S, b = blockIdx.x / S;
    const float2* __restrict__ F = g_F + b * FROW;
    const float*  __restrict__ w = wft + (size_t)s * N_FWD;

    float2 fn = F[4096];
    float  gn = w[4096];
    float  nyr = fn.x * gn, nyi = fn.y * gn;

    float ev[4];     // pass-0 log values (same thread & columns in pass 1)

    #pragma unroll
    for (int pass = 0; pass < 2; ++pass) {
        float xr[8], xi[8];

        // stage m=1 fused with global load + spectrum multiply (+odd rotation)
        #pragma unroll
        for (int q = 0; q < 8; ++q) {
            int k = tid + q * 512;
            float2 f = F[k];
            float  g = w[k];
            float vr = f.x * g, vi = f.y * g;
            if (pass) {                        // * e^{+2 pi i k/8192} = conj(g_tw[k])
                float2 c = g_tw[k];
                float r2 = vr * c.x + vi * c.y;
                float i2 = vi * c.x - vr * c.y;
                vr = r2; vi = i2;
            }
            xr[q] = vr; xi[q] = vi;
        }
        bfly8<false>(xr, xi);
        {
            float2 t = g_tw[tid << 1];
            store8c(A, xr, xi, 8 * tid, 1, t.x, -t.y);
        }
        __syncthreads();
        inv_stage(A, Bb,  8, tid); __syncthreads();
        inv_stage(Bb, A, 64, tid); __syncthreads();

        // final stage m=512 (jm=0, W=1) fused with Nyquist + log|.| + store.
        // Thread tid produces u = tid + 512 r; needed u in [1024,3072) -> r=2..5.
        #pragma unroll
        for (int q = 0; q < 8; ++q) {
            float2 v = A[CPAD(tid + q * 512)];
            xr[q] = v.x; xi[q] = v.y;
        }
        bfly8<false>(xr, xi);

        float nr = pass ? -nyr : nyr;
        float ni = pass ? -nyi : nyi;
        if (pass == 0) {
            #pragma unroll
            for (int r = 2; r <= 5; ++r) {
                float a = xr[r] + nr, bb = xi[r] + ni;
                ev[r - 2] = fmaf(0.5f, __logf(a * a + bb * bb), LOG_OFF);
            }
        } else {
            float2* o2 = (float2*)(out + (size_t)blockIdx.x * T_LEN);
            #pragma unroll
            for (int r = 2; r <= 5; ++r) {
                float a = xr[r] + nr, bb = xi[r] + ni;
                float lg = fmaf(0.5f, __logf(a * a + bb * bb), LOG_OFF);
                o2[tid + 512 * (r - 2)] = make_float2(ev[r - 2], lg);
            }
        }
        __syncthreads();
    }
}

// ---------------------------------------------------------------------------
extern "C" void kernel_launch(void* const* d_in, const int* in_sizes, int n_in,
                              void* d_out, int out_size)
{
    const float* in  = (const float*)d_in[0];
    const float* wft = (const float*)d_in[1];
    float* out = (float*)d_out;

    const int B = in_sizes[0] / T_LEN;     // 64
    const int S = in_sizes[1] / N_FWD;     // 75

    const int fwd_smem = 4 * FWD_PAD * sizeof(float);      // 147456 B
    const int cwt_smem = 2 * INV_CPAD * sizeof(float2);    //  73728 B
    cudaFuncSetAttribute(fwd_fft_kernel,
                         cudaFuncAttributeMaxDynamicSharedMemorySize, fwd_smem);
    cudaFuncSetAttribute(cwt_kernel,
                         cudaFuncAttributeMaxDynamicSharedMemorySize, cwt_smem);

    twiddle_init_kernel<<<16, 256>>>();
    fwd_fft_kernel<<<B, FTH, fwd_smem>>>(in);
    cwt_kernel<<<B * S, ITH, cwt_smem>>>(wft, out, S);
}